// round 1
// baseline (speedup 1.0000x reference)
#include <cuda_runtime.h>
#include <cstdint>
#include <cstddef>

// ---------------------------------------------------------------------------
// feature_embedding: out = concat(dyn*gcn(struct,adj_f,Wf,bf),
//                                 dyn*gcn(struct,adj_b,Wb,bb)) * sigmoid(stat@W_emb + b_emb)
// B=4, N=2048, DEST=64, NET=256, INPUT=448
// ---------------------------------------------------------------------------

namespace {
constexpr int kB     = 4;
constexpr int kN     = 2048;
constexpr int kDEST  = 64;
constexpr int kINPUT = 448;   // NET + 3*DEST
constexpr int kH     = 256;   // scratch width: [h_f(128) | h_b(128)]
constexpr int MT     = 64;    // M tile
constexpr int KT     = 32;    // K tile
constexpr int AP     = 68;    // padded 64  (68*4B = 272B, 16B-aligned rows)
constexpr int SP     = 132;   // padded 128 (132*4B = 528B, 16B-aligned rows)
}

// scratch: H = [adj_f@struct | adj_b@struct], 4*2048*256 fp32 = 8 MB
__device__ float g_H[(size_t)kB * kN * kH];

__device__ __forceinline__ unsigned long long pack2(float x) {
    unsigned long long r;
    asm("mov.b64 %0, {%1, %2};" : "=l"(r) : "f"(x), "f"(x));
    return r;
}
__device__ __forceinline__ void fma2(unsigned long long& d,
                                     unsigned long long a,
                                     unsigned long long b) {
    // packed f32x2 FMA: 2 fp32 FMAs per instruction (full-rate path on sm_103a)
    asm("fma.rn.f32x2 %0, %1, %2, %0;" : "+l"(d) : "l"(a), "l"(b));
}

// ---------------------------------------------------------------------------
// Kernel A: H[b,m, 0:128]  = sum_n adj_f[b,m,n] * struct[b,n,:]
//           H[b,m,128:256] = sum_n adj_b[b,m,n] * struct[b,n,:]
// grid (kN/MT, kB), 256 threads. Per-thread microtile: 4 rows x 8 cols, x2 mats.
// ---------------------------------------------------------------------------
__global__ void __launch_bounds__(256) gcn_kernel(const float* __restrict__ nf,
                                                  const float* __restrict__ adjF,
                                                  const float* __restrict__ adjB) {
    __shared__ float sAF[KT][AP];   // adj_f tile, transposed [k][m]
    __shared__ float sAB[KT][AP];   // adj_b tile, transposed [k][m]
    __shared__ float sS [KT][SP];   // struct tile [k][c]

    const int tid = threadIdx.x;
    const int tr  = tid >> 4;       // 0..15 -> rows tr*4 .. tr*4+3
    const int tc  = tid & 15;       // 0..15 -> cols {tc*4..+3, 64+tc*4..+3}
    const int m0  = blockIdx.x * MT;
    const int b   = blockIdx.y;

    const float* aF = adjF + (size_t)b * kN * kN;
    const float* aB = adjB + (size_t)b * kN * kN;
    const float* st = nf + (size_t)b * kN * kINPUT + kDEST;  // struct slice base

    unsigned long long accF[4][4];
    unsigned long long accB[4][4];
#pragma unroll
    for (int i = 0; i < 4; ++i)
#pragma unroll
        for (int p = 0; p < 4; ++p) { accF[i][p] = 0ull; accB[i][p] = 0ull; }

    for (int k0 = 0; k0 < kN; k0 += KT) {
        // adj tiles: 64(m) x 32(k), float4 along k (coalesced), scatter-transpose
#pragma unroll
        for (int it = 0; it < 2; ++it) {
            int idx = it * 256 + tid;       // 0..511
            int m   = idx >> 3;             // 0..63
            int kq  = idx & 7;              // 0..7
            const float4 vF = *(const float4*)(aF + (size_t)(m0 + m) * kN + k0 + kq * 4);
            const float4 vB = *(const float4*)(aB + (size_t)(m0 + m) * kN + k0 + kq * 4);
            sAF[kq*4+0][m] = vF.x; sAF[kq*4+1][m] = vF.y;
            sAF[kq*4+2][m] = vF.z; sAF[kq*4+3][m] = vF.w;
            sAB[kq*4+0][m] = vB.x; sAB[kq*4+1][m] = vB.y;
            sAB[kq*4+2][m] = vB.z; sAB[kq*4+3][m] = vB.w;
        }
        // struct tile: 32(k) x 128(c)
#pragma unroll
        for (int it = 0; it < 4; ++it) {
            int idx = it * 256 + tid;       // 0..1023
            int kr  = idx >> 5;             // 0..31
            int cq  = idx & 31;             // 0..31
            *(float4*)&sS[kr][cq*4] =
                *(const float4*)(st + (size_t)(k0 + kr) * kINPUT + cq * 4);
        }
        __syncthreads();

#pragma unroll 8
        for (int kk = 0; kk < KT; ++kk) {
            const float4 afv = *(const float4*)&sAF[kk][tr*4];
            const float4 abv = *(const float4*)&sAB[kk][tr*4];
            const ulonglong2 sp0 = *(const ulonglong2*)&sS[kk][tc*4];
            const ulonglong2 sp1 = *(const ulonglong2*)&sS[kk][64 + tc*4];
            unsigned long long sv[4]  = { sp0.x, sp0.y, sp1.x, sp1.y };
            unsigned long long af2[4] = { pack2(afv.x), pack2(afv.y), pack2(afv.z), pack2(afv.w) };
            unsigned long long ab2[4] = { pack2(abv.x), pack2(abv.y), pack2(abv.z), pack2(abv.w) };
#pragma unroll
            for (int i = 0; i < 4; ++i)
#pragma unroll
                for (int p = 0; p < 4; ++p) {
                    fma2(accF[i][p], af2[i], sv[p]);
                    fma2(accB[i][p], ab2[i], sv[p]);
                }
        }
        __syncthreads();
    }

    // write H (pairs are already in memory order: low word = even col)
#pragma unroll
    for (int i = 0; i < 4; ++i) {
        float* dst = g_H + (size_t)(b * kN + m0 + tr*4 + i) * kH;
        *(ulonglong2*)(dst +       tc*4) = make_ulonglong2(accF[i][0], accF[i][1]);
        *(ulonglong2*)(dst +  64 + tc*4) = make_ulonglong2(accF[i][2], accF[i][3]);
        *(ulonglong2*)(dst + 128 + tc*4) = make_ulonglong2(accB[i][0], accB[i][1]);
        *(ulonglong2*)(dst + 192 + tc*4) = make_ulonglong2(accB[i][2], accB[i][3]);
    }
}

// ---------------------------------------------------------------------------
// Kernel B: fused epilogue.
//   code[r, 0:64]   = H[r,  0:128] @ Wf + bf      (K-tiles 0..3)
//   code[r, 64:128] = H[r,128:256] @ Wb + bb      (K-tiles 4..7)
//   gate[r, :]      = sigmoid(stat[r,:] @ W_emb + b_emb)   (all 8 K-tiles)
//   out[r, c]       = code * dyn[r, c & 63] * gate
// grid (kB*kN/MT), 256 threads.
// ---------------------------------------------------------------------------
__global__ void __launch_bounds__(256) epilogue_kernel(
    const float* __restrict__ nf,
    const float* __restrict__ Wf, const float* __restrict__ bfv,
    const float* __restrict__ Wb, const float* __restrict__ bbv,
    const float* __restrict__ We, const float* __restrict__ be,
    float* __restrict__ out) {
    __shared__ float sH [KT][AP];   // H tile, transposed [k][r]
    __shared__ float sT [KT][AP];   // stat tile, transposed [k][r]
    __shared__ float sWc[KT][AP];   // Wf or Wb tile [k][0:64]
    __shared__ float sWe[KT][SP];   // W_emb tile [k][0:128]

    const int tid = threadIdx.x;
    const int tr  = tid >> 4;
    const int tc  = tid & 15;
    const int r0  = blockIdx.x * MT;

    float accC[4][8] = {};   // j<4: fwd cols tc*4+j ; j>=4: bwd cols 64+tc*4+(j-4)
    float accG[4][8] = {};

    for (int t = 0; t < 8; ++t) {
        const int k0 = t * KT;
        // H and stat tiles: 64(r) x 32(k), transpose on store
#pragma unroll
        for (int it = 0; it < 2; ++it) {
            int idx = it * 256 + tid;
            int rr  = idx >> 3;
            int kq  = idx & 7;
            const float4 v = *(const float4*)(g_H + (size_t)(r0 + rr) * kH + k0 + kq * 4);
            sH[kq*4+0][rr] = v.x; sH[kq*4+1][rr] = v.y;
            sH[kq*4+2][rr] = v.z; sH[kq*4+3][rr] = v.w;
            const float4 w = *(const float4*)(nf + (size_t)(r0 + rr) * kINPUT + 3*kDEST + k0 + kq * 4);
            sT[kq*4+0][rr] = w.x; sT[kq*4+1][rr] = w.y;
            sT[kq*4+2][rr] = w.z; sT[kq*4+3][rr] = w.w;
        }
        // code weights: Wf rows [k0,k0+32) for t<4, Wb rows [k0-128, ...) otherwise
        {
            const float* W = (t < 4) ? Wf : Wb;
            const int kb = (t < 4) ? k0 : (k0 - 128);
#pragma unroll
            for (int it = 0; it < 2; ++it) {
                int idx = it * 256 + tid;
                int kr  = idx >> 4;
                int cq  = idx & 15;
                *(float4*)&sWc[kr][cq*4] = *(const float4*)(W + (size_t)(kb + kr) * 64 + cq * 4);
            }
        }
        // emb weights: 32 x 128
#pragma unroll
        for (int it = 0; it < 4; ++it) {
            int idx = it * 256 + tid;
            int kr  = idx >> 5;
            int cq  = idx & 31;
            *(float4*)&sWe[kr][cq*4] = *(const float4*)(We + (size_t)(k0 + kr) * 128 + cq * 4);
        }
        __syncthreads();

        if (t < 4) {
#pragma unroll 8
            for (int kk = 0; kk < KT; ++kk) {
                const float4 h4 = *(const float4*)&sH [kk][tr*4];
                const float4 s4 = *(const float4*)&sT [kk][tr*4];
                const float4 wc = *(const float4*)&sWc[kk][tc*4];
                const float4 w0 = *(const float4*)&sWe[kk][tc*4];
                const float4 w1 = *(const float4*)&sWe[kk][64 + tc*4];
                const float hv[4]  = { h4.x, h4.y, h4.z, h4.w };
                const float sv[4]  = { s4.x, s4.y, s4.z, s4.w };
                const float wcv[4] = { wc.x, wc.y, wc.z, wc.w };
                const float w0v[4] = { w0.x, w0.y, w0.z, w0.w };
                const float w1v[4] = { w1.x, w1.y, w1.z, w1.w };
#pragma unroll
                for (int i = 0; i < 4; ++i)
#pragma unroll
                    for (int q = 0; q < 4; ++q) {
                        accG[i][q]   += sv[i] * w0v[q];
                        accG[i][4+q] += sv[i] * w1v[q];
                        accC[i][q]   += hv[i] * wcv[q];
                    }
            }
        } else {
#pragma unroll 8
            for (int kk = 0; kk < KT; ++kk) {
                const float4 h4 = *(const float4*)&sH [kk][tr*4];
                const float4 s4 = *(const float4*)&sT [kk][tr*4];
                const float4 wc = *(const float4*)&sWc[kk][tc*4];
                const float4 w0 = *(const float4*)&sWe[kk][tc*4];
                const float4 w1 = *(const float4*)&sWe[kk][64 + tc*4];
                const float hv[4]  = { h4.x, h4.y, h4.z, h4.w };
                const float sv[4]  = { s4.x, s4.y, s4.z, s4.w };
                const float wcv[4] = { wc.x, wc.y, wc.z, wc.w };
                const float w0v[4] = { w0.x, w0.y, w0.z, w0.w };
                const float w1v[4] = { w1.x, w1.y, w1.z, w1.w };
#pragma unroll
                for (int i = 0; i < 4; ++i)
#pragma unroll
                    for (int q = 0; q < 4; ++q) {
                        accG[i][q]   += sv[i] * w0v[q];
                        accG[i][4+q] += sv[i] * w1v[q];
                        accC[i][4+q] += hv[i] * wcv[q];
                    }
            }
        }
        __syncthreads();
    }

    // finalize: bias, sigmoid gate, dyn multiply, vectorized store
#pragma unroll
    for (int i = 0; i < 4; ++i) {
        const int r = r0 + tr*4 + i;
        const float4 d4 = *(const float4*)(nf + (size_t)r * kINPUT + tc*4);  // dyn
        const float dv[4] = { d4.x, d4.y, d4.z, d4.w };
        float res0[4], res1[4];
#pragma unroll
        for (int q = 0; q < 4; ++q) {
            const int c0 = tc*4 + q;        // fwd col (0..63)
            const int c1 = 64 + tc*4 + q;   // bwd col (64..127)
            const float code0 = accC[i][q]     + bfv[c0];
            const float code1 = accC[i][4 + q] + bbv[c0];
            const float g0 = 1.0f / (1.0f + __expf(-(accG[i][q]     + be[c0])));
            const float g1 = 1.0f / (1.0f + __expf(-(accG[i][4 + q] + be[c1])));
            res0[q] = code0 * dv[q] * g0;
            res1[q] = code1 * dv[q] * g1;
        }
        *(float4*)(out + (size_t)r * 128 +       tc*4) = make_float4(res0[0], res0[1], res0[2], res0[3]);
        *(float4*)(out + (size_t)r * 128 +  64 + tc*4) = make_float4(res1[0], res1[1], res1[2], res1[3]);
    }
}

// ---------------------------------------------------------------------------
extern "C" void kernel_launch(void* const* d_in, const int* in_sizes, int n_in,
                              void* d_out, int out_size) {
    (void)in_sizes; (void)n_in; (void)out_size;
    const float* nf   = (const float*)d_in[0];
    const float* adjF = (const float*)d_in[1];
    const float* adjB = (const float*)d_in[2];
    const float* Wf   = (const float*)d_in[3];
    const float* bfv  = (const float*)d_in[4];
    const float* Wb   = (const float*)d_in[5];
    const float* bbv  = (const float*)d_in[6];
    const float* We   = (const float*)d_in[7];
    const float* be   = (const float*)d_in[8];
    float* out = (float*)d_out;

    dim3 gridA(kN / MT, kB);                       // 32 x 4 = 128 blocks
    gcn_kernel<<<gridA, 256>>>(nf, adjF, adjB);

    const int gridB = (kB * kN) / MT;              // 128 blocks
    epilogue_kernel<<<gridB, 256>>>(nf, Wf, bfv, Wb, bbv, We, be, out);
}

// round 3
// speedup vs baseline: 2.3544x; 2.3544x over previous
#include <cuda_runtime.h>
#include <cstdint>
#include <cstddef>

// ===========================================================================
// feature_embedding on GB300 (PTX target sm_103 base -> no tcgen05; use
// mma.sync tf32 tensor cores + cp.async multistage pipeline).
//  H = [adj_f @ struct | adj_b @ struct]
//  out = concat(dyn*(Hf@Wf+bf), dyn*(Hb@Wb+bb)) * sigmoid(stat@W_emb+b_emb)
//  B=4, N=2048, DEST=64, NET=256, INPUT=448
// ===========================================================================

namespace {
constexpr int kB     = 4;
constexpr int kN     = 2048;
constexpr int kINPUT = 448;
constexpr int kH     = 256;      // [h_f(128) | h_b(128)]
constexpr int BM     = 128;
constexpr int BK     = 32;
constexpr int S      = 4;                        // pipeline stages
constexpr int NUM_K  = kN / BK;                  // 64
constexpr int TILE_BYTES  = BM * BK * 4;         // 16 KB
constexpr int STAGE_BYTES = 2 * TILE_BYTES;      // 32 KB (A + B)
constexpr int SMEM_TOTAL  = S * STAGE_BYTES;     // 128 KB
}

// scratch: structT (tf32-rounded) [b][feat 128][node 2048] + H
__device__ __align__(1024) float g_Bt[(size_t)kB * 128 * kN];
__device__ __align__(1024) float g_H [(size_t)kB * kN * kH];

// ---------------------------------------------------------------------------
// helpers (base compute_103 features only)
// ---------------------------------------------------------------------------
__device__ __forceinline__ uint32_t smem_u32(const void* p) {
    uint32_t a;
    asm("{ .reg .u64 t; cvta.to.shared.u64 t, %1; cvt.u32.u64 %0, t; }"
        : "=r"(a) : "l"(p));
    return a;
}
__device__ __forceinline__ void cp_async16(uint32_t dst, const void* src) {
    asm volatile("cp.async.cg.shared.global [%0], [%1], 16;"
                 :: "r"(dst), "l"(src) : "memory");
}
__device__ __forceinline__ void cp_commit() {
    asm volatile("cp.async.commit_group;" ::: "memory");
}
template <int N>
__device__ __forceinline__ void cp_wait() {
    asm volatile("cp.async.wait_group %0;" :: "n"(N) : "memory");
}
__device__ __forceinline__ uint32_t lds_u32(uint32_t addr) {
    uint32_t v;
    asm volatile("ld.shared.b32 %0, [%1];" : "=r"(v) : "r"(addr));
    return v;
}
__device__ __forceinline__ uint32_t tf32_rna_u(float x) {
    uint32_t u;
    asm("cvt.rna.tf32.f32 %0, %1;" : "=r"(u) : "f"(x));
    return u;
}
__device__ __forceinline__ float tf32_rn(float x) {
    return __uint_as_float(tf32_rna_u(x));
}
// D += A(16x8) * B(8x8), tf32 inputs, fp32 accumulate
__device__ __forceinline__ void mma_tf32(float c[4], const uint32_t a[4],
                                         const uint32_t b[2]) {
    asm volatile(
        "mma.sync.aligned.m16n8k8.row.col.f32.tf32.tf32.f32 "
        "{%0,%1,%2,%3}, {%4,%5,%6,%7}, {%8,%9}, {%0,%1,%2,%3};"
        : "+f"(c[0]), "+f"(c[1]), "+f"(c[2]), "+f"(c[3])
        : "r"(a[0]), "r"(a[1]), "r"(a[2]), "r"(a[3]), "r"(b[0]), "r"(b[1]));
}

// ---------------------------------------------------------------------------
// Pre-pass: g_Bt[b][feat][node] = tf32_rn(nf[b][node][64+feat])
// ---------------------------------------------------------------------------
__global__ void __launch_bounds__(256) transpose_struct(const float* __restrict__ nf) {
    __shared__ float t[32][33];
    const int b  = blockIdx.z;
    const int n0 = blockIdx.x * 32;
    const int f0 = blockIdx.y * 32;
    const int tx = threadIdx.x;          // 0..31
    const int ty = threadIdx.y;          // 0..7
#pragma unroll
    for (int j = 0; j < 32; j += 8)
        t[ty + j][tx] = tf32_rn(nf[((size_t)(b * kN + n0 + ty + j)) * kINPUT + 64 + f0 + tx]);
    __syncthreads();
#pragma unroll
    for (int j = 0; j < 32; j += 8)
        g_Bt[((size_t)b * 128 + f0 + ty + j) * kN + n0 + tx] = t[tx][ty + j];
}

// ---------------------------------------------------------------------------
// Kernel A: H-tile[128,128] = adj_tile[128,2048] @ structT[128,2048]^T
// grid (16, 4, 2) = (m-tile, batch, mat{f,b}); 256 threads (8 warps).
// Warp tile 64x32 (2x4 warp grid), mma.m16n8k8 tf32, 4-stage cp.async.
// SMEM tiles XOR-swizzled: float4 column pv = vec ^ (row & 7)  (stride 32).
// ---------------------------------------------------------------------------
__global__ void __launch_bounds__(256, 1) gcn_mma_kernel(
    const float* __restrict__ adjF, const float* __restrict__ adjB) {
    extern __shared__ char smem[];
    const uint32_t sb = smem_u32(smem);

    const int tid  = threadIdx.x;
    const int warp = tid >> 5;
    const int lane = tid & 31;
    const int lr   = lane >> 2;          // 0..7
    const int lc   = lane & 3;           // 0..3
    const int wm   = (warp >> 2) * 64;   // 0 | 64
    const int wn   = (warp & 3) * 32;    // 0 | 32 | 64 | 96

    const int m0  = blockIdx.x * BM;
    const int b   = blockIdx.y;
    const int mat = blockIdx.z;
    const float* adj = mat ? adjB : adjF;

    // ---- per-thread gmem src pointers + swizzled smem dst offsets ----
    const int rrow = tid >> 3;           // 0..31
    const int vec  = tid & 7;            // 0..7
    const float* srcA[4];
    const float* srcB[4];
    uint32_t dstOff[4];
#pragma unroll
    for (int q = 0; q < 4; ++q) {
        const int row = q * 32 + rrow;   // 0..127
        srcA[q] = adj  + ((size_t)(b * kN + m0 + row)) * kN + vec * 4;
        srcB[q] = g_Bt + ((size_t)(b * 128 + row)) * kN + vec * 4;
        dstOff[q] = (uint32_t)(row * 128 + ((vec ^ (row & 7)) * 16));
    }

    // ---- fragment smem base addresses (ks = 0) ----
    uint32_t aB[4], bB[4];
#pragma unroll
    for (int mf = 0; mf < 4; ++mf) {
        const int m = wm + mf * 16 + lr;     // m & 7 == lr
        aB[mf] = (uint32_t)(m * 128 + lr * 16 + lc * 4);
    }
#pragma unroll
    for (int nf = 0; nf < 4; ++nf) {
        const int n = wn + nf * 8 + lr;      // n & 7 == lr
        bB[nf] = (uint32_t)(n * 128 + lr * 16 + lc * 4);
    }

    float c[4][4][4];
#pragma unroll
    for (int mf = 0; mf < 4; ++mf)
#pragma unroll
        for (int nf = 0; nf < 4; ++nf)
#pragma unroll
            for (int r = 0; r < 4; ++r) c[mf][nf][r] = 0.0f;

    // ---- prologue: fill S-1 stages ----
#pragma unroll
    for (int s = 0; s < S - 1; ++s) {
        const uint32_t sa = sb + s * STAGE_BYTES;
        const uint32_t sbt = sa + TILE_BYTES;
        const int kof = s * BK;
#pragma unroll
        for (int q = 0; q < 4; ++q) {
            cp_async16(sa  + dstOff[q], srcA[q] + kof);
            cp_async16(sbt + dstOff[q], srcB[q] + kof);
        }
        cp_commit();
    }

    // ---- mainloop ----
    for (int i = 0; i < NUM_K; ++i) {
        cp_wait<S - 2>();
        __syncthreads();

        // issue next stage (overwrites stage computed at iter i-1)
        if (i + S - 1 < NUM_K) {
            const int s = (i + S - 1) % S;
            const uint32_t sa = sb + s * STAGE_BYTES;
            const uint32_t sbt = sa + TILE_BYTES;
            const int kof = (i + S - 1) * BK;
#pragma unroll
            for (int q = 0; q < 4; ++q) {
                cp_async16(sa  + dstOff[q], srcA[q] + kof);
                cp_async16(sbt + dstOff[q], srcB[q] + kof);
            }
            cp_commit();
        } else {
            cp_commit();   // keep wait_group accounting uniform
        }

        // compute on stage i%S
        const uint32_t sa = sb + (i % S) * STAGE_BYTES;
        const uint32_t sbt = sa + TILE_BYTES;
#pragma unroll
        for (int ks = 0; ks < 4; ++ks) {
            const uint32_t kx = (uint32_t)(ks * 32);
            uint32_t a[4][4];
#pragma unroll
            for (int mf = 0; mf < 4; ++mf) {
                const uint32_t ad = (sa + aB[mf]) ^ kx;
                a[mf][0] = tf32_rna_u(__uint_as_float(lds_u32(ad)));
                a[mf][1] = tf32_rna_u(__uint_as_float(lds_u32(ad + 1024)));
                a[mf][2] = tf32_rna_u(__uint_as_float(lds_u32(ad ^ 16)));
                a[mf][3] = tf32_rna_u(__uint_as_float(lds_u32((ad + 1024) ^ 16)));
            }
            uint32_t bfr[4][2];
#pragma unroll
            for (int nf = 0; nf < 4; ++nf) {
                const uint32_t bd = (sbt + bB[nf]) ^ kx;
                bfr[nf][0] = lds_u32(bd);        // pre-rounded tf32
                bfr[nf][1] = lds_u32(bd ^ 16);
            }
#pragma unroll
            for (int mf = 0; mf < 4; ++mf)
#pragma unroll
                for (int nf = 0; nf < 4; ++nf)
                    mma_tf32(c[mf][nf], a[mf], bfr[nf]);
        }
    }

    // ---- write C -> g_H ----
#pragma unroll
    for (int mf = 0; mf < 4; ++mf) {
        const int row = m0 + wm + mf * 16 + lr;
        float* base = g_H + ((size_t)(b * kN + row)) * kH + mat * 128;
#pragma unroll
        for (int nf = 0; nf < 4; ++nf) {
            const int col = wn + nf * 8 + lc * 2;
            *(float2*)(base + col)            = make_float2(c[mf][nf][0], c[mf][nf][1]);
            *(float2*)(base + 8 * kH + col)   = make_float2(c[mf][nf][2], c[mf][nf][3]);
        }
    }
}

// ---------------------------------------------------------------------------
// Kernel B: fused epilogue (32-row tiles, 256 blocks, 256 threads)
// ---------------------------------------------------------------------------
namespace { constexpr int KT2 = 32; constexpr int MT2 = 32; }

__global__ void __launch_bounds__(256) epilogue_kernel(
    const float* __restrict__ nf,
    const float* __restrict__ Wf, const float* __restrict__ bfv,
    const float* __restrict__ Wb, const float* __restrict__ bbv,
    const float* __restrict__ We, const float* __restrict__ be,
    float* __restrict__ out) {
    __shared__ float sH [KT2][33];
    __shared__ float sT [KT2][33];
    __shared__ float sWc[KT2][68];
    __shared__ float sWe[KT2][132];

    const int tid = threadIdx.x;
    const int tr  = tid >> 4;    // 0..15 -> rows tr*2, tr*2+1
    const int tc  = tid & 15;    // 0..15 -> cols tc*4..+3 (both halves)
    const int r0  = blockIdx.x * MT2;

    float accC[2][8] = {};
    float accG[2][8] = {};

    for (int t = 0; t < 8; ++t) {
        const int k0 = t * KT2;
        {
            const int rr = tid >> 3;
            const int kq = tid & 7;
            const float4 v = *(const float4*)(g_H + (size_t)(r0 + rr) * kH + k0 + kq * 4);
            sH[kq * 4 + 0][rr] = v.x; sH[kq * 4 + 1][rr] = v.y;
            sH[kq * 4 + 2][rr] = v.z; sH[kq * 4 + 3][rr] = v.w;
            const float4 w = *(const float4*)(nf + (size_t)(r0 + rr) * kINPUT + 192 + k0 + kq * 4);
            sT[kq * 4 + 0][rr] = w.x; sT[kq * 4 + 1][rr] = w.y;
            sT[kq * 4 + 2][rr] = w.z; sT[kq * 4 + 3][rr] = w.w;
        }
        {
            const float* W = (t < 4) ? Wf : Wb;
            const int kb = (t < 4) ? k0 : (k0 - 128);
#pragma unroll
            for (int it = 0; it < 2; ++it) {
                int idx = it * 256 + tid;
                int kr  = idx >> 4;
                int cq  = idx & 15;
                *(float4*)&sWc[kr][cq * 4] = *(const float4*)(W + (size_t)(kb + kr) * 64 + cq * 4);
            }
        }
#pragma unroll
        for (int it = 0; it < 4; ++it) {
            int idx = it * 256 + tid;
            int kr  = idx >> 5;
            int cq  = idx & 31;
            *(float4*)&sWe[kr][cq * 4] = *(const float4*)(We + (size_t)(k0 + kr) * 128 + cq * 4);
        }
        __syncthreads();

        if (t < 4) {
#pragma unroll 8
            for (int kk = 0; kk < KT2; ++kk) {
                const float hv[2] = { sH[kk][tr * 2], sH[kk][tr * 2 + 1] };
                const float sv[2] = { sT[kk][tr * 2], sT[kk][tr * 2 + 1] };
                const float4 wc = *(const float4*)&sWc[kk][tc * 4];
                const float4 w0 = *(const float4*)&sWe[kk][tc * 4];
                const float4 w1 = *(const float4*)&sWe[kk][64 + tc * 4];
                const float wcv[4] = { wc.x, wc.y, wc.z, wc.w };
                const float w0v[4] = { w0.x, w0.y, w0.z, w0.w };
                const float w1v[4] = { w1.x, w1.y, w1.z, w1.w };
#pragma unroll
                for (int i = 0; i < 2; ++i)
#pragma unroll
                    for (int q = 0; q < 4; ++q) {
                        accG[i][q]     += sv[i] * w0v[q];
                        accG[i][4 + q] += sv[i] * w1v[q];
                        accC[i][q]     += hv[i] * wcv[q];
                    }
            }
        } else {
#pragma unroll 8
            for (int kk = 0; kk < KT2; ++kk) {
                const float hv[2] = { sH[kk][tr * 2], sH[kk][tr * 2 + 1] };
                const float sv[2] = { sT[kk][tr * 2], sT[kk][tr * 2 + 1] };
                const float4 wc = *(const float4*)&sWc[kk][tc * 4];
                const float4 w0 = *(const float4*)&sWe[kk][tc * 4];
                const float4 w1 = *(const float4*)&sWe[kk][64 + tc * 4];
                const float wcv[4] = { wc.x, wc.y, wc.z, wc.w };
                const float w0v[4] = { w0.x, w0.y, w0.z, w0.w };
                const float w1v[4] = { w1.x, w1.y, w1.z, w1.w };
#pragma unroll
                for (int i = 0; i < 2; ++i)
#pragma unroll
                    for (int q = 0; q < 4; ++q) {
                        accG[i][q]     += sv[i] * w0v[q];
                        accG[i][4 + q] += sv[i] * w1v[q];
                        accC[i][4 + q] += hv[i] * wcv[q];
                    }
            }
        }
        __syncthreads();
    }

#pragma unroll
    for (int i = 0; i < 2; ++i) {
        const int r = r0 + tr * 2 + i;
        const float4 d4 = *(const float4*)(nf + (size_t)r * kINPUT + tc * 4);  // dyn
        const float dv[4] = { d4.x, d4.y, d4.z, d4.w };
        float res0[4], res1[4];
#pragma unroll
        for (int q = 0; q < 4; ++q) {
            const int c0 = tc * 4 + q;
            const int c1 = 64 + tc * 4 + q;
            const float code0 = accC[i][q]     + bfv[c0];
            const float code1 = accC[i][4 + q] + bbv[c0];
            const float g0 = 1.0f / (1.0f + __expf(-(accG[i][q]     + be[c0])));
            const float g1 = 1.0f / (1.0f + __expf(-(accG[i][4 + q] + be[c1])));
            res0[q] = code0 * dv[q] * g0;
            res1[q] = code1 * dv[q] * g1;
        }
        *(float4*)(out + (size_t)r * 128 +      tc * 4) = make_float4(res0[0], res0[1], res0[2], res0[3]);
        *(float4*)(out + (size_t)r * 128 + 64 + tc * 4) = make_float4(res1[0], res1[1], res1[2], res1[3]);
    }
}

// ---------------------------------------------------------------------------
extern "C" void kernel_launch(void* const* d_in, const int* in_sizes, int n_in,
                              void* d_out, int out_size) {
    (void)in_sizes; (void)n_in; (void)out_size;
    const float* nf   = (const float*)d_in[0];
    const float* adjF = (const float*)d_in[1];
    const float* adjB = (const float*)d_in[2];
    const float* Wf   = (const float*)d_in[3];
    const float* bfv  = (const float*)d_in[4];
    const float* Wb   = (const float*)d_in[5];
    const float* bbv  = (const float*)d_in[6];
    const float* We   = (const float*)d_in[7];
    const float* be   = (const float*)d_in[8];
    float* out = (float*)d_out;

    static bool attr_set = false;
    if (!attr_set) {
        cudaFuncSetAttribute(gcn_mma_kernel,
                             cudaFuncAttributeMaxDynamicSharedMemorySize, SMEM_TOTAL);
        attr_set = true;
    }

    transpose_struct<<<dim3(kN / 32, 128 / 32, kB), dim3(32, 8)>>>(nf);
    gcn_mma_kernel<<<dim3(kN / BM, kB, 2), 256, SMEM_TOTAL>>>(adjF, adjB);
    epilogue_kernel<<<(kB * kN) / MT2, 256>>>(nf, Wf, bfv, Wb, bbv, We, be, out);
}

// round 4
// speedup vs baseline: 2.3922x; 1.0161x over previous
#include <cuda_runtime.h>
#include <cuda_fp16.h>
#include <cstdint>
#include <cstddef>

// ===========================================================================
// feature_embedding on GB300 (base compute_103: mma.sync fp16 tensor cores).
//  H = [adj_f @ struct | adj_b @ struct]   (fp16 operands, fp32 accumulate)
//  out = concat(dyn*(Hf@Wf+bf), dyn*(Hb@Wb+bb)) * sigmoid(stat@W_emb+b_emb)
//  B=4, N=2048, DEST=64, NET=256, INPUT=448
// ===========================================================================

namespace {
constexpr int kB     = 4;
constexpr int kN     = 2048;
constexpr int kINPUT = 448;
constexpr int kH     = 256;          // [h_f(128) | h_b(128)]
constexpr int BM     = 128;
constexpr int BK     = 32;           // k per iter (2 x m16n8k16)
constexpr int SB     = 4;            // B cp.async stages
constexpr int NUM_K  = kN / BK;      // 64
constexpr int TILE_B16 = 128 * BK * 2;          // 8 KB fp16 tile
constexpr int A_REGION = 2 * TILE_B16;          // A double buffer 16 KB
constexpr int SMEM_TOTAL = A_REGION + SB * TILE_B16;   // 48 KB
}

// scratch: structT fp16 [b][feat 128][node 2048] (2 MB) + H fp32 (8 MB)
__device__ __align__(1024) __half g_Bt[(size_t)kB * 128 * kN];
__device__ __align__(1024) float  g_H [(size_t)kB * kN * kH];

// ---------------------------------------------------------------------------
// helpers
// ---------------------------------------------------------------------------
__device__ __forceinline__ uint32_t smem_u32(const void* p) {
    uint32_t a;
    asm("{ .reg .u64 t; cvta.to.shared.u64 t, %1; cvt.u32.u64 %0, t; }"
        : "=r"(a) : "l"(p));
    return a;
}
__device__ __forceinline__ void cp_async16(uint32_t dst, const void* src) {
    asm volatile("cp.async.cg.shared.global [%0], [%1], 16;"
                 :: "r"(dst), "l"(src) : "memory");
}
__device__ __forceinline__ void cp_commit() {
    asm volatile("cp.async.commit_group;" ::: "memory");
}
template <int N>
__device__ __forceinline__ void cp_wait() {
    asm volatile("cp.async.wait_group %0;" :: "n"(N) : "memory");
}
__device__ __forceinline__ uint32_t lds_u32(uint32_t addr) {
    uint32_t v;
    asm volatile("ld.shared.b32 %0, [%1];" : "=r"(v) : "r"(addr));
    return v;
}
__device__ __forceinline__ void sts_v4(uint32_t addr, uint32_t x, uint32_t y,
                                       uint32_t z, uint32_t w) {
    asm volatile("st.shared.v4.b32 [%0], {%1,%2,%3,%4};"
                 :: "r"(addr), "r"(x), "r"(y), "r"(z), "r"(w) : "memory");
}
__device__ __forceinline__ uint32_t pack_h2(float lo, float hi) {
    __half2 h = __floats2half2_rn(lo, hi);   // .x = lo (low 16 bits)
    return *reinterpret_cast<uint32_t*>(&h);
}
// D += A(16x16) * B(16x8), fp16 inputs, fp32 accumulate
__device__ __forceinline__ void mma_f16(float c[4], const uint32_t a[4],
                                        const uint32_t b[2]) {
    asm volatile(
        "mma.sync.aligned.m16n8k16.row.col.f32.f16.f16.f32 "
        "{%0,%1,%2,%3}, {%4,%5,%6,%7}, {%8,%9}, {%0,%1,%2,%3};"
        : "+f"(c[0]), "+f"(c[1]), "+f"(c[2]), "+f"(c[3])
        : "r"(a[0]), "r"(a[1]), "r"(a[2]), "r"(a[3]), "r"(b[0]), "r"(b[1]));
}

// ---------------------------------------------------------------------------
// Pre-pass: g_Bt[b][feat][node] = fp16(nf[b][node][64+feat])
// ---------------------------------------------------------------------------
__global__ void __launch_bounds__(256) transpose_struct(const float* __restrict__ nf) {
    __shared__ float t[32][33];
    const int b  = blockIdx.z;
    const int n0 = blockIdx.x * 32;
    const int f0 = blockIdx.y * 32;
    const int tx = threadIdx.x;          // 0..31
    const int ty = threadIdx.y;          // 0..7
#pragma unroll
    for (int j = 0; j < 32; j += 8)
        t[ty + j][tx] = nf[((size_t)(b * kN + n0 + ty + j)) * kINPUT + 64 + f0 + tx];
    __syncthreads();
#pragma unroll
    for (int j = 0; j < 32; j += 8)
        g_Bt[((size_t)b * 128 + f0 + ty + j) * kN + n0 + tx] = __float2half_rn(t[tx][ty + j]);
}

// ---------------------------------------------------------------------------
// Kernel A: H-tile[128,128] = adj_tile[128,2048] @ structT[128,2048]^T
// grid (16, 4, 2) = (m-tile, batch, mat{f,b}); 256 threads (8 warps).
// A: gmem fp32 -> regs -> cvt fp16 -> swizzled SMEM (double buffer).
// B: fp16 from g_Bt via 4-stage cp.async.
// SMEM fp16 tiles: 128 rows x 64B, 16B-block phys = vlog ^ ((row>>1)&3).
// Warp tile 64x32, mma.m16n8k16 fp16/fp32.
// ---------------------------------------------------------------------------
__global__ void __launch_bounds__(256, 1) gcn_mma_kernel(
    const float* __restrict__ adjF, const float* __restrict__ adjB) {
    extern __shared__ char smem[];
    const uint32_t sbA = smem_u32(smem);                 // A16: 2 x 8 KB
    const uint32_t sbB = sbA + A_REGION;                 // B16: SB x 8 KB

    const int tid  = threadIdx.x;
    const int warp = tid >> 5;
    const int lane = tid & 31;
    const int lr   = lane >> 2;          // 0..7
    const int lc   = lane & 3;           // 0..3
    const int wm   = (warp >> 2) * 64;   // 0 | 64
    const int wn   = (warp & 3) * 32;    // 0 | 32 | 64 | 96

    const int m0  = blockIdx.x * BM;
    const int b   = blockIdx.y;
    const int mat = blockIdx.z;
    const float* adj = mat ? adjB : adjF;

    // ---- A loader per-thread geometry (2 x 16B-blocks per iter) ----
    int   rowA[2], vlogA[2];
    const float* srcA[2];
    uint32_t dstA[2];
#pragma unroll
    for (int q = 0; q < 2; ++q) {
        const int idx = q * 256 + tid;       // 0..511
        rowA[q]  = idx >> 2;                 // 0..127
        vlogA[q] = idx & 3;                  // 0..3
        srcA[q]  = adj + ((size_t)(b * kN + m0 + rowA[q])) * kN + vlogA[q] * 8;
        dstA[q]  = (uint32_t)(rowA[q] * 64 + ((vlogA[q] ^ ((rowA[q] >> 1) & 3)) * 16));
    }

    // ---- B loader per-thread geometry ----
    const __half* srcB[2];
    uint32_t dstB[2];
#pragma unroll
    for (int q = 0; q < 2; ++q) {
        const int idx = q * 256 + tid;
        const int row = idx >> 2;
        const int vl  = idx & 3;
        srcB[q] = g_Bt + ((size_t)(b * 128 + row)) * kN + vl * 8;
        dstB[q] = (uint32_t)(row * 64 + ((vl ^ ((row >> 1) & 3)) * 16));
    }

    // ---- fragment base addresses (ks=0, include swizzle key) ----
    const uint32_t keyx = (uint32_t)(((lr >> 1) & 3) * 16);
    uint32_t aBase[4], bBase[4];
#pragma unroll
    for (int mf = 0; mf < 4; ++mf)
        aBase[mf] = (uint32_t)((wm + mf * 16 + lr) * 64) ^ keyx;
#pragma unroll
    for (int nf = 0; nf < 4; ++nf)
        bBase[nf] = (uint32_t)((wn + nf * 8 + lr) * 64) ^ keyx;
    const uint32_t lcx = (uint32_t)(lc * 4);

    float c[4][4][4];
#pragma unroll
    for (int mf = 0; mf < 4; ++mf)
#pragma unroll
        for (int nf = 0; nf < 4; ++nf)
#pragma unroll
            for (int r = 0; r < 4; ++r) c[mf][nf][r] = 0.0f;

    // ---- prologue ----
    // B stages 0..SB-2
#pragma unroll
    for (int s = 0; s < SB - 1; ++s) {
#pragma unroll
        for (int q = 0; q < 2; ++q)
            cp_async16(sbB + s * TILE_B16 + dstB[q], srcB[q] + s * BK);
        cp_commit();
    }
    // A tile 0 -> regs
    float4 rA[2][2];
#pragma unroll
    for (int q = 0; q < 2; ++q) {
        rA[q][0] = *(const float4*)(srcA[q]);
        rA[q][1] = *(const float4*)(srcA[q] + 4);
    }

    // ---- mainloop ----
    for (int i = 0; i < NUM_K; ++i) {
        cp_wait<SB - 2>();        // B tile i arrived
        __syncthreads();          // B(i) visible; A16 slot (i&1) free

        // convert + store A tile i
        const uint32_t aSlot = sbA + (uint32_t)((i & 1) * TILE_B16);
#pragma unroll
        for (int q = 0; q < 2; ++q) {
            const uint32_t w0 = pack_h2(rA[q][0].x, rA[q][0].y);
            const uint32_t w1 = pack_h2(rA[q][0].z, rA[q][0].w);
            const uint32_t w2 = pack_h2(rA[q][1].x, rA[q][1].y);
            const uint32_t w3 = pack_h2(rA[q][1].z, rA[q][1].w);
            sts_v4(aSlot + dstA[q], w0, w1, w2, w3);
        }
        // prefetch A tile i+1
        if (i + 1 < NUM_K) {
            const int kof = (i + 1) * BK;
#pragma unroll
            for (int q = 0; q < 2; ++q) {
                rA[q][0] = *(const float4*)(srcA[q] + kof);
                rA[q][1] = *(const float4*)(srcA[q] + kof + 4);
            }
        }
        // issue B tile i+SB-1
        if (i + SB - 1 < NUM_K) {
            const int s = (i + SB - 1) % SB;
            const int kof = (i + SB - 1) * BK;
#pragma unroll
            for (int q = 0; q < 2; ++q)
                cp_async16(sbB + s * TILE_B16 + dstB[q], srcB[q] + kof);
        }
        cp_commit();

        __syncthreads();          // A16(i) visible to all warps

        const uint32_t bSlot = sbB + (uint32_t)((i % SB) * TILE_B16);
#pragma unroll
        for (int ks = 0; ks < 2; ++ks) {
            const uint32_t kx = (uint32_t)(ks * 32);
            uint32_t a[4][4];
#pragma unroll
            for (int mf = 0; mf < 4; ++mf) {
                const uint32_t ad = (aSlot + ((aBase[mf] ^ kx) + lcx));
                a[mf][0] = lds_u32(ad);
                a[mf][1] = lds_u32(ad + 512);        // row +8
                a[mf][2] = lds_u32(ad ^ 16);         // k +8
                a[mf][3] = lds_u32((ad + 512) ^ 16);
            }
            uint32_t bf[4][2];
#pragma unroll
            for (int nf = 0; nf < 4; ++nf) {
                const uint32_t bd = (bSlot + ((bBase[nf] ^ kx) + lcx));
                bf[nf][0] = lds_u32(bd);
                bf[nf][1] = lds_u32(bd ^ 16);
            }
#pragma unroll
            for (int mf = 0; mf < 4; ++mf)
#pragma unroll
                for (int nf = 0; nf < 4; ++nf)
                    mma_f16(c[mf][nf], a[mf], bf[nf]);
        }
    }

    // ---- write C -> g_H ----
#pragma unroll
    for (int mf = 0; mf < 4; ++mf) {
        const int row = m0 + wm + mf * 16 + lr;
        float* base = g_H + ((size_t)(b * kN + row)) * kH + mat * 128;
#pragma unroll
        for (int nf = 0; nf < 4; ++nf) {
            const int col = wn + nf * 8 + lc * 2;
            *(float2*)(base + col)          = make_float2(c[mf][nf][0], c[mf][nf][1]);
            *(float2*)(base + 8 * kH + col) = make_float2(c[mf][nf][2], c[mf][nf][3]);
        }
    }
}

// ---------------------------------------------------------------------------
// Kernel B: fused epilogue (32-row tiles, 256 blocks, 256 threads)
// ---------------------------------------------------------------------------
namespace { constexpr int KT2 = 32; constexpr int MT2 = 32; }

__global__ void __launch_bounds__(256) epilogue_kernel(
    const float* __restrict__ nf,
    const float* __restrict__ Wf, const float* __restrict__ bfv,
    const float* __restrict__ Wb, const float* __restrict__ bbv,
    const float* __restrict__ We, const float* __restrict__ be,
    float* __restrict__ out) {
    __shared__ float sH [KT2][33];
    __shared__ float sT [KT2][33];
    __shared__ float sWc[KT2][68];
    __shared__ float sWe[KT2][132];

    const int tid = threadIdx.x;
    const int tr  = tid >> 4;    // 0..15 -> rows tr*2, tr*2+1
    const int tc  = tid & 15;    // 0..15 -> cols tc*4..+3 (both halves)
    const int r0  = blockIdx.x * MT2;

    float accC[2][8] = {};
    float accG[2][8] = {};

    for (int t = 0; t < 8; ++t) {
        const int k0 = t * KT2;
        {
            const int rr = tid >> 3;
            const int kq = tid & 7;
            const float4 v = *(const float4*)(g_H + (size_t)(r0 + rr) * kH + k0 + kq * 4);
            sH[kq * 4 + 0][rr] = v.x; sH[kq * 4 + 1][rr] = v.y;
            sH[kq * 4 + 2][rr] = v.z; sH[kq * 4 + 3][rr] = v.w;
            const float4 w = *(const float4*)(nf + (size_t)(r0 + rr) * kINPUT + 192 + k0 + kq * 4);
            sT[kq * 4 + 0][rr] = w.x; sT[kq * 4 + 1][rr] = w.y;
            sT[kq * 4 + 2][rr] = w.z; sT[kq * 4 + 3][rr] = w.w;
        }
        {
            const float* W = (t < 4) ? Wf : Wb;
            const int kb = (t < 4) ? k0 : (k0 - 128);
#pragma unroll
            for (int it = 0; it < 2; ++it) {
                int idx = it * 256 + tid;
                int kr  = idx >> 4;
                int cq  = idx & 15;
                *(float4*)&sWc[kr][cq * 4] = *(const float4*)(W + (size_t)(kb + kr) * 64 + cq * 4);
            }
        }
#pragma unroll
        for (int it = 0; it < 4; ++it) {
            int idx = it * 256 + tid;
            int kr  = idx >> 5;
            int cq  = idx & 31;
            *(float4*)&sWe[kr][cq * 4] = *(const float4*)(We + (size_t)(k0 + kr) * 128 + cq * 4);
        }
        __syncthreads();

        if (t < 4) {
#pragma unroll 8
            for (int kk = 0; kk < KT2; ++kk) {
                const float hv[2] = { sH[kk][tr * 2], sH[kk][tr * 2 + 1] };
                const float sv[2] = { sT[kk][tr * 2], sT[kk][tr * 2 + 1] };
                const float4 wc = *(const float4*)&sWc[kk][tc * 4];
                const float4 w0 = *(const float4*)&sWe[kk][tc * 4];
                const float4 w1 = *(const float4*)&sWe[kk][64 + tc * 4];
                const float wcv[4] = { wc.x, wc.y, wc.z, wc.w };
                const float w0v[4] = { w0.x, w0.y, w0.z, w0.w };
                const float w1v[4] = { w1.x, w1.y, w1.z, w1.w };
#pragma unroll
                for (int i = 0; i < 2; ++i)
#pragma unroll
                    for (int q = 0; q < 4; ++q) {
                        accG[i][q]     += sv[i] * w0v[q];
                        accG[i][4 + q] += sv[i] * w1v[q];
                        accC[i][q]     += hv[i] * wcv[q];
                    }
            }
        } else {
#pragma unroll 8
            for (int kk = 0; kk < KT2; ++kk) {
                const float hv[2] = { sH[kk][tr * 2], sH[kk][tr * 2 + 1] };
                const float sv[2] = { sT[kk][tr * 2], sT[kk][tr * 2 + 1] };
                const float4 wc = *(const float4*)&sWc[kk][tc * 4];
                const float4 w0 = *(const float4*)&sWe[kk][tc * 4];
                const float4 w1 = *(const float4*)&sWe[kk][64 + tc * 4];
                const float wcv[4] = { wc.x, wc.y, wc.z, wc.w };
                const float w0v[4] = { w0.x, w0.y, w0.z, w0.w };
                const float w1v[4] = { w1.x, w1.y, w1.z, w1.w };
#pragma unroll
                for (int i = 0; i < 2; ++i)
#pragma unroll
                    for (int q = 0; q < 4; ++q) {
                        accG[i][q]     += sv[i] * w0v[q];
                        accG[i][4 + q] += sv[i] * w1v[q];
                        accC[i][4 + q] += hv[i] * wcv[q];
                    }
            }
        }
        __syncthreads();
    }

#pragma unroll
    for (int i = 0; i < 2; ++i) {
        const int r = r0 + tr * 2 + i;
        const float4 d4 = *(const float4*)(nf + (size_t)r * kINPUT + tc * 4);  // dyn
        const float dv[4] = { d4.x, d4.y, d4.z, d4.w };
        float res0[4], res1[4];
#pragma unroll
        for (int q = 0; q < 4; ++q) {
            const int c0 = tc * 4 + q;
            const int c1 = 64 + tc * 4 + q;
            const float code0 = accC[i][q]     + bfv[c0];
            const float code1 = accC[i][4 + q] + bbv[c0];
            const float g0 = 1.0f / (1.0f + __expf(-(accG[i][q]     + be[c0])));
            const float g1 = 1.0f / (1.0f + __expf(-(accG[i][4 + q] + be[c1])));
            res0[q] = code0 * dv[q] * g0;
            res1[q] = code1 * dv[q] * g1;
        }
        *(float4*)(out + (size_t)r * 128 +      tc * 4) = make_float4(res0[0], res0[1], res0[2], res0[3]);
        *(float4*)(out + (size_t)r * 128 + 64 + tc * 4) = make_float4(res1[0], res1[1], res1[2], res1[3]);
    }
}

// ---------------------------------------------------------------------------
extern "C" void kernel_launch(void* const* d_in, const int* in_sizes, int n_in,
                              void* d_out, int out_size) {
    (void)in_sizes; (void)n_in; (void)out_size;
    const float* nf   = (const float*)d_in[0];
    const float* adjF = (const float*)d_in[1];
    const float* adjB = (const float*)d_in[2];
    const float* Wf   = (const float*)d_in[3];
    const float* bfv  = (const float*)d_in[4];
    const float* Wb   = (const float*)d_in[5];
    const float* bbv  = (const float*)d_in[6];
    const float* We   = (const float*)d_in[7];
    const float* be   = (const float*)d_in[8];
    float* out = (float*)d_out;

    static bool attr_set = false;
    if (!attr_set) {
        cudaFuncSetAttribute(gcn_mma_kernel,
                             cudaFuncAttributeMaxDynamicSharedMemorySize, SMEM_TOTAL);
        attr_set = true;
    }

    transpose_struct<<<dim3(kN / 32, 128 / 32, kB), dim3(32, 8)>>>(nf);
    gcn_mma_kernel<<<dim3(kN / BM, kB, 2), 256, SMEM_TOTAL>>>(adjF, adjB);
    epilogue_kernel<<<(kB * kN) / MT2, 256>>>(nf, Wf, bfv, Wb, bbv, We, be, out);
}

// round 6
// speedup vs baseline: 3.3910x; 1.4175x over previous
#include <cuda_runtime.h>
#include <cuda_fp16.h>
#include <cstdint>
#include <cstddef>

// ===========================================================================
// feature_embedding on GB300 (base compute_103: mma.sync fp16 tensor cores).
//  H16 = [adj_f @ struct | adj_b @ struct]   (fp16 operands + fp16 result)
//  out = concat(dyn*(Hf@Wf+bf), dyn*(Hb@Wb+bb)) * sigmoid(stat@W_emb+b_emb)
//  Epilogue runs on tensor cores too (code gemm K=128, gate gemm K=256).
//  B=4, N=2048, DEST=64, NET=256, INPUT=448
// ===========================================================================

namespace {
constexpr int kB     = 4;
constexpr int kN     = 2048;
constexpr int kINPUT = 448;
constexpr int BM     = 128;
constexpr int BK     = 32;           // k per iter (2 x m16n8k16)
constexpr int SB     = 4;            // B cp.async stages
constexpr int NUM_K  = kN / BK;      // 64
constexpr int TILE_B16 = 128 * BK * 2;          // 8 KB fp16 tile
constexpr int A_REGION = 2 * TILE_B16;          // A double buffer 16 KB
constexpr int SMEM_GCN = A_REGION + SB * TILE_B16;   // 48 KB

// epilogue smem layout (bytes)
constexpr int oH  = 0;            // H16 tile  128 x 272B
constexpr int oWc = 34816;        // WcT       64 x 272B
constexpr int oS  = 52224;        // stat16    128 x 528B
constexpr int oWe = 119808;       // WeT slice 64 x 528B
constexpr int SMEM_EPI = 153600;
}

// scratch
__device__ __align__(1024) __half g_Bt   [(size_t)kB * 128 * kN];   // structT fp16
__device__ __align__(1024) __half g_H16  [(size_t)kB * kN * 256];   // [hf|hb] fp16
__device__ __align__(1024) __half g_stat16[(size_t)kB * kN * 256];  // stat fp16
__device__ __align__(256)  __half g_WcT  [2 * 64 * 128];            // [mat][n][k]
__device__ __align__(256)  __half g_WeT  [128 * 256];               // [n][k]

// ---------------------------------------------------------------------------
// helpers
// ---------------------------------------------------------------------------
__device__ __forceinline__ uint32_t smem_u32(const void* p) {
    uint32_t a;
    asm("{ .reg .u64 t; cvta.to.shared.u64 t, %1; cvt.u32.u64 %0, t; }"
        : "=r"(a) : "l"(p));
    return a;
}
__device__ __forceinline__ void cp_async16(uint32_t dst, const void* src) {
    asm volatile("cp.async.cg.shared.global [%0], [%1], 16;"
                 :: "r"(dst), "l"(src) : "memory");
}
__device__ __forceinline__ void cp_commit() {
    asm volatile("cp.async.commit_group;" ::: "memory");
}
template <int N>
__device__ __forceinline__ void cp_wait() {
    asm volatile("cp.async.wait_group %0;" :: "n"(N) : "memory");
}
__device__ __forceinline__ uint32_t lds_u32(uint32_t addr) {
    uint32_t v;
    asm volatile("ld.shared.b32 %0, [%1];" : "=r"(v) : "r"(addr));
    return v;
}
__device__ __forceinline__ void sts_v4(uint32_t addr, uint32_t x, uint32_t y,
                                       uint32_t z, uint32_t w) {
    asm volatile("st.shared.v4.b32 [%0], {%1,%2,%3,%4};"
                 :: "r"(addr), "r"(x), "r"(y), "r"(z), "r"(w) : "memory");
}
__device__ __forceinline__ uint32_t pack_h2(float lo, float hi) {
    __half2 h = __floats2half2_rn(lo, hi);
    return *reinterpret_cast<uint32_t*>(&h);
}
// D += A(16x16) * B(16x8), fp16 in, fp32 accumulate
__device__ __forceinline__ void mma_f16(float c[4], const uint32_t a[4],
                                        const uint32_t b[2]) {
    asm volatile(
        "mma.sync.aligned.m16n8k16.row.col.f32.f16.f16.f32 "
        "{%0,%1,%2,%3}, {%4,%5,%6,%7}, {%8,%9}, {%0,%1,%2,%3};"
        : "+f"(c[0]), "+f"(c[1]), "+f"(c[2]), "+f"(c[3])
        : "r"(a[0]), "r"(a[1]), "r"(a[2]), "r"(a[3]), "r"(b[0]), "r"(b[1]));
}

// ---------------------------------------------------------------------------
// Prep kernels
// ---------------------------------------------------------------------------
__global__ void __launch_bounds__(256) transpose_struct(const float* __restrict__ nfeat) {
    __shared__ float t[32][33];
    const int b  = blockIdx.z;
    const int n0 = blockIdx.x * 32;
    const int f0 = blockIdx.y * 32;
    const int tx = threadIdx.x;
    const int ty = threadIdx.y;
#pragma unroll
    for (int j = 0; j < 32; j += 8)
        t[ty + j][tx] = nfeat[((size_t)(b * kN + n0 + ty + j)) * kINPUT + 64 + f0 + tx];
    __syncthreads();
#pragma unroll
    for (int j = 0; j < 32; j += 8)
        g_Bt[((size_t)b * 128 + f0 + ty + j) * kN + n0 + tx] = __float2half_rn(t[tx][ty + j]);
}

__global__ void __launch_bounds__(256) prep_weights(
    const float* __restrict__ Wf, const float* __restrict__ Wb,
    const float* __restrict__ We) {
    const int t = blockIdx.x * 256 + threadIdx.x;        // grid 64 -> 16384 threads
    for (int i = t; i < 128 * 256; i += 16384) {
        const int n = i >> 8, k = i & 255;
        g_WeT[i] = __float2half_rn(We[k * 128 + n]);
    }
    for (int i = t; i < 64 * 128; i += 16384) {
        const int n = i >> 7, k = i & 127;
        g_WcT[i]        = __float2half_rn(Wf[k * 64 + n]);
        g_WcT[8192 + i] = __float2half_rn(Wb[k * 64 + n]);
    }
}

__global__ void __launch_bounds__(256) cvt_stat(const float* __restrict__ nfeat) {
    const int t = blockIdx.x * 256 + threadIdx.x;        // grid 512 -> 131072 threads
    for (int i = t; i < kB * kN * 64; i += 131072) {     // float4 units
        const int row = i >> 6, c4 = i & 63;
        const float4 v = *(const float4*)(nfeat + (size_t)row * kINPUT + 192 + c4 * 4);
        uint32_t* d = reinterpret_cast<uint32_t*>(g_stat16 + (size_t)row * 256 + c4 * 4);
        d[0] = pack_h2(v.x, v.y);
        d[1] = pack_h2(v.z, v.w);
    }
}

// ---------------------------------------------------------------------------
// Kernel A: H16-tile[128,128] = adj_tile[128,2048] @ structT[128,2048]^T
// grid (16, 4, 2); 256 threads (8 warps). ONE __syncthreads per k-iter.
// ---------------------------------------------------------------------------
__global__ void __launch_bounds__(256, 1) gcn_mma_kernel(
    const float* __restrict__ adjF, const float* __restrict__ adjB) {
    extern __shared__ char smem[];
    const uint32_t sbA = smem_u32(smem);                 // A16: 2 x 8 KB
    const uint32_t sbB = sbA + A_REGION;                 // B16: SB x 8 KB

    const int tid  = threadIdx.x;
    const int warp = tid >> 5;
    const int lane = tid & 31;
    const int lr   = lane >> 2;
    const int lc   = lane & 3;
    const int wm   = (warp >> 2) * 64;
    const int wn   = (warp & 3) * 32;

    const int m0  = blockIdx.x * BM;
    const int b   = blockIdx.y;
    const int mat = blockIdx.z;
    const float* adj = mat ? adjB : adjF;

    // A loader geometry
    const float* srcA[2];
    uint32_t dstA[2];
#pragma unroll
    for (int q = 0; q < 2; ++q) {
        const int idx = q * 256 + tid;
        const int row = idx >> 2;
        const int vl  = idx & 3;
        srcA[q] = adj + ((size_t)(b * kN + m0 + row)) * kN + vl * 8;
        dstA[q] = (uint32_t)(row * 64 + ((vl ^ ((row >> 1) & 3)) * 16));
    }
    // B loader geometry
    const __half* srcB[2];
    uint32_t dstB[2];
#pragma unroll
    for (int q = 0; q < 2; ++q) {
        const int idx = q * 256 + tid;
        const int row = idx >> 2;
        const int vl  = idx & 3;
        srcB[q] = g_Bt + ((size_t)(b * 128 + row)) * kN + vl * 8;
        dstB[q] = (uint32_t)(row * 64 + ((vl ^ ((row >> 1) & 3)) * 16));
    }

    // fragment base addresses
    const uint32_t keyx = (uint32_t)(((lr >> 1) & 3) * 16);
    uint32_t aBase[4], bBase[4];
#pragma unroll
    for (int mf = 0; mf < 4; ++mf)
        aBase[mf] = (uint32_t)((wm + mf * 16 + lr) * 64) ^ keyx;
#pragma unroll
    for (int nb = 0; nb < 4; ++nb)
        bBase[nb] = (uint32_t)((wn + nb * 8 + lr) * 64) ^ keyx;
    const uint32_t lcx = (uint32_t)(lc * 4);

    float c[4][4][4];
#pragma unroll
    for (int mf = 0; mf < 4; ++mf)
#pragma unroll
        for (int nb = 0; nb < 4; ++nb)
#pragma unroll
            for (int r = 0; r < 4; ++r) c[mf][nb][r] = 0.0f;

    // ---- prologue ----
#pragma unroll
    for (int s = 0; s < SB - 1; ++s) {
#pragma unroll
        for (int q = 0; q < 2; ++q)
            cp_async16(sbB + s * TILE_B16 + dstB[q], srcB[q] + s * BK);
        cp_commit();
    }
    float4 rA[2][2];
#pragma unroll
    for (int q = 0; q < 2; ++q) {          // A(0) -> regs
        rA[q][0] = *(const float4*)(srcA[q]);
        rA[q][1] = *(const float4*)(srcA[q] + 4);
    }
#pragma unroll
    for (int q = 0; q < 2; ++q) {          // STS A(0) -> slot 0
        sts_v4(sbA + dstA[q],
               pack_h2(rA[q][0].x, rA[q][0].y), pack_h2(rA[q][0].z, rA[q][0].w),
               pack_h2(rA[q][1].x, rA[q][1].y), pack_h2(rA[q][1].z, rA[q][1].w));
    }
#pragma unroll
    for (int q = 0; q < 2; ++q) {          // A(1) -> regs
        rA[q][0] = *(const float4*)(srcA[q] + BK);
        rA[q][1] = *(const float4*)(srcA[q] + BK + 4);
    }

    // ---- mainloop: ONE sync per iteration ----
    for (int i = 0; i < NUM_K; ++i) {
        cp_wait<SB - 2>();        // B(i) arrived (per-thread)
        __syncthreads();          // B(i) + A16(i) visible to all

        if (i + 1 < NUM_K) {      // STS A(i+1) into idle slot
            const uint32_t aNext = sbA + (uint32_t)(((i + 1) & 1) * TILE_B16);
#pragma unroll
            for (int q = 0; q < 2; ++q) {
                sts_v4(aNext + dstA[q],
                       pack_h2(rA[q][0].x, rA[q][0].y), pack_h2(rA[q][0].z, rA[q][0].w),
                       pack_h2(rA[q][1].x, rA[q][1].y), pack_h2(rA[q][1].z, rA[q][1].w));
            }
        }
        if (i + 2 < NUM_K) {      // LDG A(i+2)
            const int kof = (i + 2) * BK;
#pragma unroll
            for (int q = 0; q < 2; ++q) {
                rA[q][0] = *(const float4*)(srcA[q] + kof);
                rA[q][1] = *(const float4*)(srcA[q] + kof + 4);
            }
        }
        if (i + SB - 1 < NUM_K) { // cp.async B(i+SB-1)
            const int s = (i + SB - 1) % SB;
            const int kof = (i + SB - 1) * BK;
#pragma unroll
            for (int q = 0; q < 2; ++q)
                cp_async16(sbB + s * TILE_B16 + dstB[q], srcB[q] + kof);
        }
        cp_commit();

        const uint32_t aSlot = sbA + (uint32_t)((i & 1) * TILE_B16);
        const uint32_t bSlot = sbB + (uint32_t)((i % SB) * TILE_B16);
#pragma unroll
        for (int ks = 0; ks < 2; ++ks) {
            const uint32_t kx = (uint32_t)(ks * 32);
            uint32_t a[4][4];
#pragma unroll
            for (int mf = 0; mf < 4; ++mf) {
                const uint32_t ad = (aSlot + ((aBase[mf] ^ kx) + lcx));
                a[mf][0] = lds_u32(ad);
                a[mf][1] = lds_u32(ad + 512);
                a[mf][2] = lds_u32(ad ^ 16);
                a[mf][3] = lds_u32((ad + 512) ^ 16);
            }
            uint32_t bf[4][2];
#pragma unroll
            for (int nb = 0; nb < 4; ++nb) {
                const uint32_t bd = (bSlot + ((bBase[nb] ^ kx) + lcx));
                bf[nb][0] = lds_u32(bd);
                bf[nb][1] = lds_u32(bd ^ 16);
            }
#pragma unroll
            for (int mf = 0; mf < 4; ++mf)
#pragma unroll
                for (int nb = 0; nb < 4; ++nb)
                    mma_f16(c[mf][nb], a[mf], bf[nb]);
        }
    }

    // ---- write C -> g_H16 (fp16) ----
#pragma unroll
    for (int mf = 0; mf < 4; ++mf) {
        const int row = m0 + wm + mf * 16 + lr;
        const size_t base = ((size_t)(b * kN + row)) * 256 + mat * 128;
#pragma unroll
        for (int nb = 0; nb < 4; ++nb) {
            const int col = wn + nb * 8 + lc * 2;
            *reinterpret_cast<uint32_t*>(g_H16 + base + col) =
                pack_h2(c[mf][nb][0], c[mf][nb][1]);
            *reinterpret_cast<uint32_t*>(g_H16 + base + 8 * 256 + col) =
                pack_h2(c[mf][nb][2], c[mf][nb][3]);
        }
    }
}

// ---------------------------------------------------------------------------
// Kernel B: mma epilogue. grid (64, 2) = (row-tile of 128, mat); 256 threads.
//   code = H16[:,mat*128:+128] @ WcT[mat]   (K=128)
//   gate = sigmoid(stat16 @ WeT[mat*64:+64] + be)  (K=256)
//   out[:, mat*64:+64] = (code + bias) * dyn * gate
// ---------------------------------------------------------------------------
__global__ void __launch_bounds__(256, 1) epilogue_mma(
    const float* __restrict__ nfeat,
    const float* __restrict__ bfv, const float* __restrict__ bbv,
    const float* __restrict__ be,  float* __restrict__ out) {
    extern __shared__ char smem[];
    const uint32_t sb = smem_u32(smem);

    const int tid  = threadIdx.x;
    const int warp = tid >> 5;
    const int lane = tid & 31;
    const int lr   = lane >> 2;
    const int lc   = lane & 3;
    const int wm   = (warp >> 2) * 64;   // rows
    const int wn   = (warp & 3) * 16;    // cols (0..63)

    const int r0  = blockIdx.x * 128;    // global row in [0, 8192)
    const int mat = blockIdx.y;

    // ---- bulk loads (one group) ----
    for (int idx = tid; idx < 2048; idx += 256) {        // H16 slice 128x128
        const int row = idx >> 4, v = idx & 15;
        cp_async16(sb + oH + row * 272 + v * 16,
                   g_H16 + ((size_t)(r0 + row)) * 256 + mat * 128 + v * 8);
    }
    for (int idx = tid; idx < 1024; idx += 256) {        // WcT 64x128
        const int row = idx >> 4, v = idx & 15;
        cp_async16(sb + oWc + row * 272 + v * 16,
                   g_WcT + mat * 64 * 128 + row * 128 + v * 8);
    }
    for (int idx = tid; idx < 4096; idx += 256) {        // stat16 128x256
        const int row = idx >> 5, v = idx & 31;
        cp_async16(sb + oS + row * 528 + v * 16,
                   g_stat16 + ((size_t)(r0 + row)) * 256 + v * 8);
    }
    for (int idx = tid; idx < 2048; idx += 256) {        // WeT slice 64x256
        const int row = idx >> 5, v = idx & 31;
        cp_async16(sb + oWe + row * 528 + v * 16,
                   g_WeT + ((size_t)(mat * 64 + row)) * 256 + v * 8);
    }
    cp_commit();
    cp_wait<0>();
    __syncthreads();

    const uint32_t lcx = (uint32_t)(lc * 4);

    // ---- gemm1: code (K = 128) ----
    float c1[4][2][4];
#pragma unroll
    for (int mf = 0; mf < 4; ++mf)
#pragma unroll
        for (int nb = 0; nb < 2; ++nb)
#pragma unroll
            for (int r = 0; r < 4; ++r) c1[mf][nb][r] = 0.0f;
#pragma unroll
    for (int ks = 0; ks < 8; ++ks) {
        const uint32_t ko = (uint32_t)(ks * 32);
        uint32_t a[4][4];
#pragma unroll
        for (int mf = 0; mf < 4; ++mf) {
            const uint32_t ad = sb + oH + (uint32_t)((wm + mf * 16 + lr) * 272) + ko + lcx;
            a[mf][0] = lds_u32(ad);
            a[mf][1] = lds_u32(ad + 8 * 272);
            a[mf][2] = lds_u32(ad + 16);
            a[mf][3] = lds_u32(ad + 8 * 272 + 16);
        }
        uint32_t bf[2][2];
#pragma unroll
        for (int nb = 0; nb < 2; ++nb) {
            const uint32_t bd = sb + oWc + (uint32_t)((wn + nb * 8 + lr) * 272) + ko + lcx;
            bf[nb][0] = lds_u32(bd);
            bf[nb][1] = lds_u32(bd + 16);
        }
#pragma unroll
        for (int mf = 0; mf < 4; ++mf)
#pragma unroll
            for (int nb = 0; nb < 2; ++nb)
                mma_f16(c1[mf][nb], a[mf], bf[nb]);
    }

    // ---- gemm2: gate (K = 256) ----
    float c2[4][2][4];
#pragma unroll
    for (int mf = 0; mf < 4; ++mf)
#pragma unroll
        for (int nb = 0; nb < 2; ++nb)
#pragma unroll
            for (int r = 0; r < 4; ++r) c2[mf][nb][r] = 0.0f;
#pragma unroll
    for (int ks = 0; ks < 16; ++ks) {
        const uint32_t ko = (uint32_t)(ks * 32);
        uint32_t a[4][4];
#pragma unroll
        for (int mf = 0; mf < 4; ++mf) {
            const uint32_t ad = sb + oS + (uint32_t)((wm + mf * 16 + lr) * 528) + ko + lcx;
            a[mf][0] = lds_u32(ad);
            a[mf][1] = lds_u32(ad + 8 * 528);
            a[mf][2] = lds_u32(ad + 16);
            a[mf][3] = lds_u32(ad + 8 * 528 + 16);
        }
        uint32_t bf[2][2];
#pragma unroll
        for (int nb = 0; nb < 2; ++nb) {
            const uint32_t bd = sb + oWe + (uint32_t)((wn + nb * 8 + lr) * 528) + ko + lcx;
            bf[nb][0] = lds_u32(bd);
            bf[nb][1] = lds_u32(bd + 16);
        }
#pragma unroll
        for (int mf = 0; mf < 4; ++mf)
#pragma unroll
            for (int nb = 0; nb < 2; ++nb)
                mma_f16(c2[mf][nb], a[mf], bf[nb]);
    }

    // ---- combine + store ----
    const float* bc = mat ? bbv : bfv;
#pragma unroll
    for (int nb = 0; nb < 2; ++nb) {
        const int cl = wn + nb * 8 + lc * 2;
        const float2 biasC = *(const float2*)(bc + cl);
        const float2 biasG = *(const float2*)(be + mat * 64 + cl);
#pragma unroll
        for (int mf = 0; mf < 4; ++mf) {
#pragma unroll
            for (int h = 0; h < 2; ++h) {
                const int row = r0 + wm + mf * 16 + lr + h * 8;
                const float2 dyn = *(const float2*)(nfeat + (size_t)row * kINPUT + cl);
                const float g0 = 1.0f / (1.0f + __expf(-(c2[mf][nb][2 * h]     + biasG.x)));
                const float g1 = 1.0f / (1.0f + __expf(-(c2[mf][nb][2 * h + 1] + biasG.y)));
                float2 o;
                o.x = (c1[mf][nb][2 * h]     + biasC.x) * dyn.x * g0;
                o.y = (c1[mf][nb][2 * h + 1] + biasC.y) * dyn.y * g1;
                *(float2*)(out + (size_t)row * 128 + mat * 64 + cl) = o;
            }
        }
    }
}

// ---------------------------------------------------------------------------
extern "C" void kernel_launch(void* const* d_in, const int* in_sizes, int n_in,
                              void* d_out, int out_size) {
    (void)in_sizes; (void)n_in; (void)out_size;
    const float* nfeat = (const float*)d_in[0];
    const float* adjF  = (const float*)d_in[1];
    const float* adjB  = (const float*)d_in[2];
    const float* Wf    = (const float*)d_in[3];
    const float* bfv   = (const float*)d_in[4];
    const float* Wb    = (const float*)d_in[5];
    const float* bbv   = (const float*)d_in[6];
    const float* We    = (const float*)d_in[7];
    const float* be    = (const float*)d_in[8];
    float* out = (float*)d_out;

    static bool attr_set = false;
    if (!attr_set) {
        cudaFuncSetAttribute(gcn_mma_kernel,
                             cudaFuncAttributeMaxDynamicSharedMemorySize, SMEM_GCN);
        cudaFuncSetAttribute(epilogue_mma,
                             cudaFuncAttributeMaxDynamicSharedMemorySize, SMEM_EPI);
        attr_set = true;
    }

    prep_weights<<<64, 256>>>(Wf, Wb, We);
    cvt_stat<<<512, 256>>>(nfeat);
    transpose_struct<<<dim3(kN / 32, 128 / 32, kB), dim3(32, 8)>>>(nfeat);
    gcn_mma_kernel<<<dim3(kN / BM, kB, 2), 256, SMEM_GCN>>>(adjF, adjB);
    epilogue_mma<<<dim3(kB * kN / 128, 2), 256, SMEM_EPI>>>(nfeat, bfv, bbv, be, out);
}